// round 15
// baseline (speedup 1.0000x reference)
#include <cuda_runtime.h>
#include <cuda_fp16.h>
#include <cstdint>

#define BB 2
#define CC 32
#define HH 128
#define WW 416
#define DD 48
#define HW_ (HH*WW)
#define CHW_ (CC*HH*WW)
#define ISCALE 0.05892556509887896f  // 1/sqrt(C*K2) = 1/sqrt(288)
#define RP 416    // row stride (halves) for Al16/Br16/xm16
#define PHW 208   // parity half-width

__device__ __forceinline__ float h16(float v) {
    return __half2float(__float2half_rn(v));
}

#define MMA16816(c0,c1,c2,c3,a0,a1,a2,a3,b0,b1) \
  asm volatile("mma.sync.aligned.m16n8k16.row.col.f32.f16.f16.f32 " \
    "{%0,%1,%2,%3}, {%4,%5,%6,%7}, {%8,%9}, {%0,%1,%2,%3};" \
    : "+f"(c0), "+f"(c1), "+f"(c2), "+f"(c3) \
    : "r"(a0), "r"(a1), "r"(a2), "r"(a3), "r"(b0), "r"(b1))

#define LDSM_X4_T(r0,r1,r2,r3,addr) \
  asm volatile("ldmatrix.sync.aligned.m8n8.x4.trans.shared.b16 {%0,%1,%2,%3}, [%4];" \
    : "=r"(r0), "=r"(r1), "=r"(r2), "=r"(r3) : "r"(addr))

__device__ __forceinline__ uint32_t smem_u32(const void* p) {
    return (uint32_t)__cvta_generic_to_shared(p);
}

// Device-global scratch (allocation forbidden)
__device__ __half g_Al16[BB*CC*HH*RP];     // RAW 3x3 box sums, fp16
__device__ __half g_Br16[BB*CC*HH*RP];
__device__ __half g_xm16[BB*CC*HH*RP];     // RAW xm, fp16
__device__ __half g_xl16[BB*CC*HH*2*PHW];  // parity-split inputs [b][c][h][q][p]
__device__ __half g_xr16[BB*CC*HH*2*PHW];
__device__ float  g_nli[BB*HW_];           // 1/max(||patch||, eps)
__device__ float  g_nri[BB*HW_];
__device__ float  g_nmi[BB*HW_];           // ISCALE/max(||xm||_c, eps)
__device__ float  g_Grow[BB*DD*HW_];

// ---------------------------------------------------------------------------
// Kernel 1: prep. z=0/1: raw box sums + parity copies + patch norms (proven
// fast path). z=2: raw fp16 xm copy + channel norms (single pass, no halos).
// ---------------------------------------------------------------------------
__global__ __launch_bounds__(128) void cv_prep_kernel(
    const float* __restrict__ xl, const float* __restrict__ xm,
    const float* __restrict__ xr)
{
    const int t    = threadIdx.x;
    const int h    = blockIdx.x;
    const int b    = blockIdx.y;
    const int img  = blockIdx.z;

    if (img == 2) {
        const int cu = t * 4;
        if (cu >= WW) return;       // t < 104
        const float* pm = xm + b*CHW_ + h*WW + cu;
        float sq0 = 0.f, sq1 = 0.f, sq2 = 0.f, sq3 = 0.f;
        #pragma unroll
        for (int c = 0; c < CC; c++) {
            float4 v = *(const float4*)(pm + c*HW_);
            sq0 += v.x*v.x; sq1 += v.y*v.y; sq2 += v.z*v.z; sq3 += v.w*v.w;
            __half2 h01 = __floats2half2_rn(v.x, v.y);
            __half2 h23 = __floats2half2_rn(v.z, v.w);
            uint2 hv;
            hv.x = *(const uint32_t*)&h01;
            hv.y = *(const uint32_t*)&h23;
            *(uint2*)&g_xm16[((b*CC + c)*HH + h)*RP + cu] = hv;
        }
        float4 n;
        n.x = ISCALE / fmaxf(sqrtf(sq0), 1e-3f);
        n.y = ISCALE / fmaxf(sqrtf(sq1), 1e-3f);
        n.z = ISCALE / fmaxf(sqrtf(sq2), 1e-3f);
        n.w = ISCALE / fmaxf(sqrtf(sq3), 1e-3f);
        *(float4*)&g_nmi[b*HW_ + h*WW + cu] = n;
        return;
    }

    const int wi   = t >> 5;
    const int lane = t & 31;
    const float* x = img ? xr : xl;
    __half* gbox   = img ? g_Br16 : g_Al16;
    __half* gq     = img ? g_xr16 : g_xl16;
    float* gn      = img ? g_nri : g_nli;

    const int cu = wi*120 + (lane - 1)*4;      // -4 .. 484, multiple of 4
    const bool ld = (cu >= 0) && (cu <= WW - 4);
    const bool wr = (lane >= 1) && (lane <= 30) && (cu <= WW - 4);
    const bool hm = (h > 0), hp = (h < HH - 1);
    const float* base = x + b*CHW_ + h*WW + (ld ? cu : 0);

    float sq0 = 0.f, sq1 = 0.f, sq2 = 0.f, sq3 = 0.f;
    const float4 z4 = make_float4(0.f, 0.f, 0.f, 0.f);

    #pragma unroll
    for (int c = 0; c < CC; c++) {
        float4 r0 = (ld && hm) ? *(const float4*)(base + c*HW_ - WW) : z4;
        float4 r1 =  ld        ? *(const float4*)(base + c*HW_)      : z4;
        float4 r2 = (ld && hp) ? *(const float4*)(base + c*HW_ + WW) : z4;
        float cs0 = r0.x + r1.x + r2.x;
        float cs1 = r0.y + r1.y + r2.y;
        float cs2 = r0.z + r1.z + r2.z;
        float cs3 = r0.w + r1.w + r2.w;
        sq0 += r0.x*r0.x + r1.x*r1.x + r2.x*r2.x;
        sq1 += r0.y*r0.y + r1.y*r1.y + r2.y*r2.y;
        sq2 += r0.z*r0.z + r1.z*r1.z + r2.z*r2.z;
        sq3 += r0.w*r0.w + r1.w*r1.w + r2.w*r2.w;
        float csm1 = __shfl_up_sync(0xffffffffu, cs3, 1);
        float csp1 = __shfl_down_sync(0xffffffffu, cs0, 1);
        if (wr) {
            __half2 b01 = __floats2half2_rn(csm1 + cs0 + cs1, cs0 + cs1 + cs2);
            __half2 b23 = __floats2half2_rn(cs1 + cs2 + cs3, cs2 + cs3 + csp1);
            uint2 bv;
            bv.x = *(const uint32_t*)&b01;
            bv.y = *(const uint32_t*)&b23;
            *(uint2*)&gbox[((b*CC + c)*HH + h)*RP + cu] = bv;
            int qb = ((b*CC + c)*HH + h)*(2*PHW) + (cu >> 1);
            *(__half2*)&gq[qb]       = __floats2half2_rn(r1.x, r1.z);  // even
            *(__half2*)&gq[qb + PHW] = __floats2half2_rn(r1.y, r1.w);  // odd
        }
    }
    float sqm1 = __shfl_up_sync(0xffffffffu, sq3, 1);
    float sqp1 = __shfl_down_sync(0xffffffffu, sq0, 1);
    if (wr) {
        float4 n;
        n.x = 1.f / fmaxf(sqrtf(sqm1 + sq0 + sq1), 1e-3f);
        n.y = 1.f / fmaxf(sqrtf(sq0 + sq1 + sq2), 1e-3f);
        n.z = 1.f / fmaxf(sqrtf(sq1 + sq2 + sq3), 1e-3f);
        n.w = 1.f / fmaxf(sqrtf(sq2 + sq3 + sqp1), 1e-3f);
        *(float4*)&gn[b*HW_ + h*WW + cu] = n;
    }
}

// ---------------------------------------------------------------------------
// Kernel 2: Grow via HMMA + ldmatrix (unchanged, proven).
// ---------------------------------------------------------------------------
#define GSL 136
#define GSR 184
#define US  264

__global__ __launch_bounds__(256) void cv_g_kernel()
{
    extern __shared__ __half gsm[];
    __half* s_XL = gsm;                              // [q][c][p_loc]
    __half* s_XR = gsm + 2*CC*GSL;                   // [q][c][j]
    __half* s_G  = gsm + 2*CC*GSL + 2*CC*GSR;        // [d][u_loc]

    const int t  = threadIdx.x;
    const int u0 = blockIdx.x * 208;
    const int r  = blockIdx.y;
    const int b  = blockIdx.z;
    const int P0 = u0/2 - 8;
    const int J0 = P0 - 48;

    for (int i = t; i < 2*CC*16; i += 256) {
        int k = i & 15, c = (i >> 4) & 31, q = i >> 9;
        int p = P0 + 8*k;
        int4 v = make_int4(0,0,0,0);
        if (p >= 0 && p <= PHW-8)
            v = *(const int4*)&g_xl16[((b*CC + c)*HH + r)*(2*PHW) + q*PHW + p];
        *(int4*)&s_XL[(q*CC + c)*GSL + 8*k] = v;
    }
    for (int i = t; i < 2*CC*22; i += 256) {
        int k = i % 22, c = (i/22) % CC, q = i / (22*CC);
        int m0 = J0 + 8*k;
        int4 v = make_int4(0,0,0,0);
        if (m0 >= 0 && m0 <= PHW-8)
            v = *(const int4*)&g_xr16[((b*CC + c)*HH + r)*(2*PHW) + q*PHW + m0];
        *(int4*)&s_XR[(q*CC + c)*GSR + 8*k] = v;
    }
    __syncthreads();

    const int wid  = t >> 5;
    const int lane = t & 31;
    const int g    = lane >> 2;
    const int tt   = lane & 3;
    const int lc   = (lane & 7) + ((lane & 16) >> 1);
    const int lm   = lane & 8;

    for (int job = wid; job < 16; job += 8) {
        const int q = job & 1;
        const int i = job >> 1;
        const uint32_t XLq = smem_u32(s_XL + q*CC*GSL);
        const uint32_t XRq = smem_u32(s_XR + q*CC*GSR);

        const int rl0 = 16*i + g, rl1 = rl0 + 8;
        uint32_t a0,a1,a2,a3,a4,a5,a6,a7;
        {
            uint32_t ad0 = XLq + (uint32_t)((lc)*GSL + 16*i + lm) * 2;
            uint32_t ad1 = ad0 + 16*GSL*2;
            LDSM_X4_T(a0,a1,a2,a3, ad0);
            LDSM_X4_T(a4,a5,a6,a7, ad1);
        }
        const int ub0 = 2*rl0 + q;
        const int ub1 = 2*rl1 + q;

        #pragma unroll
        for (int nn = 0; nn < 8; nn++) {
            const int jbase = 16*i + 8*nn;
            uint32_t b0,b1,b2,b3;
            LDSM_X4_T(b0,b1,b2,b3, XRq + (uint32_t)(lane*GSR + jbase)*2);
            float c0 = 0.f, c1 = 0.f, c2 = 0.f, c3 = 0.f;
            MMA16816(c0,c1,c2,c3, a0,a1,a2,a3, b0,b1);
            MMA16816(c0,c1,c2,c3, a4,a5,a6,a7, b2,b3);
            const int j0 = jbase + 2*tt, j1 = j0 + 1;
            int d;
            d = rl0 + 48 - j0; if (d >= 0 && d < DD) s_G[d*US + ub0] = __float2half_rn(c0);
            d = rl0 + 48 - j1; if (d >= 0 && d < DD) s_G[d*US + ub0] = __float2half_rn(c1);
            d = rl1 + 48 - j0; if (d >= 0 && d < DD) s_G[d*US + ub1] = __float2half_rn(c2);
            d = rl1 + 48 - j1; if (d >= 0 && d < DD) s_G[d*US + ub1] = __float2half_rn(c3);
        }
    }
    __syncthreads();

    for (int i = t; i < DD*52; i += 256) {
        int d = i / 52, k4 = (i % 52) * 4;
        int base = d*US + 16 + k4;
        __half2 q0 = *(const __half2*)(s_G + base - 2);
        __half2 q1 = *(const __half2*)(s_G + base);
        __half2 q2 = *(const __half2*)(s_G + base + 2);
        __half2 q3 = *(const __half2*)(s_G + base + 4);
        float gm1 = __high2float(q0);
        float g0  = __low2float(q1), g1 = __high2float(q1);
        float g2  = __low2float(q2), g3 = __high2float(q2);
        float g4  = __low2float(q3);
        float4 o;
        o.x = gm1 + g0 + g1;
        o.y = g0 + g1 + g2;
        o.z = g1 + g2 + g3;
        o.w = g2 + g3 + g4;
        *(float4*)&g_Grow[(b*DD + d)*HW_ + r*WW + u0 + k4] = o;
    }
}

// ---------------------------------------------------------------------------
// Kernel 3: LR channel -- vertical 3-tap over Grow + normalization (proven).
// ---------------------------------------------------------------------------
__global__ __launch_bounds__(416) void cv_lr_out_kernel(float* __restrict__ out)
{
    const int w  = threadIdx.x;
    const int h0 = blockIdx.x * 4;
    const int d  = blockIdx.y;
    const int b  = blockIdx.z;

    const int ob = (b*3 + 2)*DD*HW_ + d*HW_ + w;
    if (w < d || w >= WW - d) {
        #pragma unroll
        for (int r = 0; r < 4; r++) out[ob + (h0+r)*WW] = 0.f;
        return;
    }
    const int u = w + d;
    const float* gb = g_Grow + (b*DD + d)*HW_ + u;

    float v[6];
    #pragma unroll
    for (int r = 0; r < 6; r++) {
        int row = h0 - 1 + r;
        v[r] = (row >= 0 && row < HH) ? __ldg(gb + row*WW) : 0.f;
    }
    const float* pnl = g_nli + b*HW_ + u;
    const float* pnr = g_nri + b*HW_ + (w - d);
    #pragma unroll
    for (int r = 0; r < 4; r++) {
        int h = h0 + r;
        float s = v[r] + v[r+1] + v[r+2];
        float val = s * __ldg(pnl + h*WW) * __ldg(pnr + h*WW) * ISCALE;
        out[ob + h*WW] = h16(fminf(fmaxf(val, -10.f), 10.f));
    }
}

// ---------------------------------------------------------------------------
// Kernel 4: L/R channels via HMMA + ldmatrix. All fills are int4 row copies;
// ALL normalization (xm + patch) applied at band-extract. Staging [dp][w]
// (bank-conflict-free extract: (4d + g/2 + 8tt) mod 32 covers all banks),
// vectorized copy-out.
// ---------------------------------------------------------------------------
#define FS  136
#define WSJ 184
#define WS  136   // staging stride [dp][w]

__global__ __launch_bounds__(256) void cv_lrcost_kernel(float* __restrict__ out)
{
    extern __shared__ __half lsm[];
    __half* s_F  = lsm;                          // [c][w_local]
    __half* s_WA = lsm + CC*FS;                  // [c][j]
    __half* s_WB = lsm + CC*FS + CC*WSJ;         // [c][j]
    __half* s_S  = lsm + CC*FS + 2*CC*WSJ;       // [dp][w]  96 x 136
    float*  s_nA = (float*)(lsm + CC*FS + 2*CC*WSJ + 96*WS);  // [176]
    float*  s_nB = s_nA + 176;
    float*  s_nM = s_nB + 176;                   // [128]

    const int t  = threadIdx.x;
    const int u0 = blockIdx.x * 128;
    const int h  = blockIdx.y;
    const int b  = blockIdx.z;

    // F fill: raw xm fp16, 32 c x 16 int4
    for (int i = t; i < CC*16; i += 256) {
        int c = i >> 4, k = i & 15;
        int col = u0 + 8*k;
        int4 v = make_int4(0,0,0,0);
        if (col <= WW-8) v = *(const int4*)&g_xm16[((b*CC + c)*HH + h)*RP + col];
        *(int4*)&s_F[c*FS + 8*k] = v;
    }
    // WA fill
    for (int i = t; i < CC*22; i += 256) {
        int c = i / 22, k = i % 22;
        int col = u0 + 8*k;
        int4 v = make_int4(0,0,0,0);
        if (col <= WW-8) v = *(const int4*)&g_Al16[((b*CC + c)*HH + h)*RP + col];
        *(int4*)&s_WA[c*WSJ + 8*k] = v;
    }
    // WB fill
    for (int i = t; i < CC*22; i += 256) {
        int c = i / 22, k = i % 22;
        int col = u0 - 48 + 8*k;
        int4 v = make_int4(0,0,0,0);
        if (col >= 0 && col <= WW-8)
            v = *(const int4*)&g_Br16[((b*CC + c)*HH + h)*RP + col];
        *(int4*)&s_WB[c*WSJ + 8*k] = v;
    }
    // norm fills
    for (int j = t; j < 176; j += 256) {
        int colA = u0 + j;
        s_nA[j] = (colA < WW) ? g_nli[b*HW_ + h*WW + colA] : 0.f;
        int colB = u0 - 48 + j;
        s_nB[j] = (colB >= 0 && colB < WW) ? g_nri[b*HW_ + h*WW + colB] : 0.f;
    }
    for (int j = t; j < 128; j += 256) {
        int col = u0 + j;
        s_nM[j] = (col < WW) ? g_nmi[b*HW_ + h*WW + col] : 0.f;
    }
    __syncthreads();

    const int wid  = t >> 5;
    const int lane = t & 31;
    const int g    = lane >> 2;
    const int tt   = lane & 3;
    const int wl0  = wid * 16;
    const int lc   = (lane & 7) + ((lane & 16) >> 1);
    const int lm   = lane & 8;

    uint32_t a0,a1,a2,a3,a4,a5,a6,a7;
    {
        uint32_t ad0 = smem_u32(s_F) + (uint32_t)(lc*FS + wl0 + lm) * 2;
        uint32_t ad1 = ad0 + 16*FS*2;
        LDSM_X4_T(a0,a1,a2,a3, ad0);
        LDSM_X4_T(a4,a5,a6,a7, ad1);
    }

    const uint32_t WAb = smem_u32(s_WA) + (uint32_t)(lane*WSJ)*2;
    const uint32_t WBb = smem_u32(s_WB) + (uint32_t)(lane*WSJ)*2;
    const int rl0 = wl0 + g, rl1 = rl0 + 8;
    const float nm0 = s_nM[rl0], nm1 = s_nM[rl1];

    #pragma unroll
    for (int nn = 0; nn < 8; nn++) {
        const int jbase = wl0 + 8*nn;
        const int j0 = jbase + 2*tt, j1 = j0 + 1;

        {   // L side: dp = j - rl, multiplier = nm(rl) * nli(u0+j)
            uint32_t b0,b1,b2,b3;
            LDSM_X4_T(b0,b1,b2,b3, WAb + (uint32_t)jbase*2);
            float c0 = 0.f, c1 = 0.f, c2 = 0.f, c3 = 0.f;
            MMA16816(c0,c1,c2,c3, a0,a1,a2,a3, b0,b1);
            MMA16816(c0,c1,c2,c3, a4,a5,a6,a7, b2,b3);
            float fa0 = s_nA[j0], fa1 = s_nA[j1];
            int d;
            d = j0 - rl0; if (d >= 0 && d < DD)
                s_S[d*WS + rl0] = __float2half_rn(fminf(fmaxf(c0*(nm0*fa0), -10.f), 10.f));
            d = j1 - rl0; if (d >= 0 && d < DD)
                s_S[d*WS + rl0] = __float2half_rn(fminf(fmaxf(c1*(nm0*fa1), -10.f), 10.f));
            d = j0 - rl1; if (d >= 0 && d < DD)
                s_S[d*WS + rl1] = __float2half_rn(fminf(fmaxf(c2*(nm1*fa0), -10.f), 10.f));
            d = j1 - rl1; if (d >= 0 && d < DD)
                s_S[d*WS + rl1] = __float2half_rn(fminf(fmaxf(c3*(nm1*fa1), -10.f), 10.f));
        }
        {   // R side: dp = 48 + (rl + 48 - j), multiplier = nm(rl) * nri(u0-48+j)
            uint32_t b0,b1,b2,b3;
            LDSM_X4_T(b0,b1,b2,b3, WBb + (uint32_t)jbase*2);
            float c0 = 0.f, c1 = 0.f, c2 = 0.f, c3 = 0.f;
            MMA16816(c0,c1,c2,c3, a0,a1,a2,a3, b0,b1);
            MMA16816(c0,c1,c2,c3, a4,a5,a6,a7, b2,b3);
            float fb0 = s_nB[j0], fb1 = s_nB[j1];
            int d;
            d = rl0 + 48 - j0; if (d >= 0 && d < DD)
                s_S[(48+d)*WS + rl0] = __float2half_rn(fminf(fmaxf(c0*(nm0*fb0), -10.f), 10.f));
            d = rl0 + 48 - j1; if (d >= 0 && d < DD)
                s_S[(48+d)*WS + rl0] = __float2half_rn(fminf(fmaxf(c1*(nm0*fb1), -10.f), 10.f));
            d = rl1 + 48 - j0; if (d >= 0 && d < DD)
                s_S[(48+d)*WS + rl1] = __float2half_rn(fminf(fmaxf(c2*(nm1*fb0), -10.f), 10.f));
            d = rl1 + 48 - j1; if (d >= 0 && d < DD)
                s_S[(48+d)*WS + rl1] = __float2half_rn(fminf(fmaxf(c3*(nm1*fb1), -10.f), 10.f));
        }
    }
    __syncthreads();

    // Vectorized copy-out: 96 dp x 16 int4 (8 halves each).
    const int wlim = min(128, WW - u0);
    const int obase = (b*3)*DD*HW_ + h*WW + u0;
    for (int i = t; i < 96*16; i += 256) {
        int dp = i >> 4, k = i & 15;
        int w8 = 8*k;
        if (w8 < wlim) {
            int4 v = *(const int4*)&s_S[dp*WS + w8];
            const __half* hv = (const __half*)&v;
            float4 o1, o2;
            o1.x = __half2float(hv[0]); o1.y = __half2float(hv[1]);
            o1.z = __half2float(hv[2]); o1.w = __half2float(hv[3]);
            o2.x = __half2float(hv[4]); o2.y = __half2float(hv[5]);
            o2.z = __half2float(hv[6]); o2.w = __half2float(hv[7]);
            *(float4*)&out[obase + dp*HW_ + w8]     = o1;
            *(float4*)&out[obase + dp*HW_ + w8 + 4] = o2;
        }
    }
}

// ---------------------------------------------------------------------------
extern "C" void kernel_launch(void* const* d_in, const int* in_sizes, int n_in,
                              void* d_out, int out_size)
{
    const float* xl = (const float*)d_in[0];
    const float* xm = (const float*)d_in[1];
    const float* xr = (const float*)d_in[2];
    float* out = (float*)d_out;

    const int smem_g  = (2*CC*GSL + 2*CC*GSR + DD*US) * (int)sizeof(__half);      // 66304
    const int smem_lr = (CC*FS + 2*CC*WSJ + 96*WS) * (int)sizeof(__half)
                        + (176*2 + 128) * (int)sizeof(float);                      // ~60,288
    cudaFuncSetAttribute(cv_g_kernel,
        cudaFuncAttributeMaxDynamicSharedMemorySize, smem_g);
    cudaFuncSetAttribute(cv_lrcost_kernel,
        cudaFuncAttributeMaxDynamicSharedMemorySize, smem_lr);

    cv_prep_kernel<<<dim3(HH, BB, 3), 128>>>(xl, xm, xr);
    cv_g_kernel<<<dim3(2, HH, BB), 256, smem_g>>>();
    cv_lr_out_kernel<<<dim3(HH/4, DD, BB), 416>>>(out);
    cv_lrcost_kernel<<<dim3(4, HH, BB), 256, smem_lr>>>(out);
}